// round 15
// baseline (speedup 1.0000x reference)
#include <cuda_runtime.h>
#include <cuda_bf16.h>

typedef unsigned int U32;
typedef unsigned long long U64;

__device__ __forceinline__ U32 tf32r(float x) {
    U32 r;
    asm("cvt.rna.tf32.f32 %0, %1;" : "=r"(r) : "f"(x));
    return r;
}
__device__ __forceinline__ float2 add2(float2 a, float2 b) {
    U64 ua = *reinterpret_cast<U64*>(&a);
    U64 ub = *reinterpret_cast<U64*>(&b);
    U64 uc;
    asm("add.rn.f32x2 %0, %1, %2;" : "=l"(uc) : "l"(ua), "l"(ub));
    return *reinterpret_cast<float2*>(&uc);
}
__device__ __forceinline__ void mma_tf32(
    float& c0, float& c1, float& c2, float& c3,
    U32 a0, U32 a1, U32 a2, U32 a3, U32 b0, U32 b1)
{
    asm volatile(
        "mma.sync.aligned.m16n8k8.row.col.f32.tf32.tf32.f32 "
        "{%0,%1,%2,%3}, {%4,%5,%6,%7}, {%8,%9}, {%0,%1,%2,%3};"
        : "+f"(c0), "+f"(c1), "+f"(c2), "+f"(c3)
        : "r"(a0), "r"(a1), "r"(a2), "r"(a3), "r"(b0), "r"(b1));
}
__device__ __forceinline__ void mma_bf16(
    float& c0, float& c1, float& c2, float& c3,
    U32 a0, U32 a1, U32 a2, U32 a3, U32 b0, U32 b1)
{
    asm volatile(
        "mma.sync.aligned.m16n8k16.row.col.f32.bf16.bf16.f32 "
        "{%0,%1,%2,%3}, {%4,%5,%6,%7}, {%8,%9}, {%0,%1,%2,%3};"
        : "+f"(c0), "+f"(c1), "+f"(c2), "+f"(c3)
        : "r"(a0), "r"(a1), "r"(a2), "r"(a3), "r"(b0), "r"(b1));
}
__device__ __forceinline__ void cp16(U32 dst, const void* src) {
    asm volatile("cp.async.ca.shared.global [%0], [%1], 16;" :: "r"(dst), "l"(src));
}
__device__ __forceinline__ void cp_commit() { asm volatile("cp.async.commit_group;"); }
__device__ __forceinline__ void cp_wait2()  { asm volatile("cp.async.wait_group 2;"); }
__device__ __forceinline__ void cp_wait0()  { asm volatile("cp.async.wait_group 0;"); }

// bf16 hi/lo split. a = hi + lo + r, |r| <= 2^-18 |a|
__device__ __forceinline__ void bsplit(float v, unsigned short& hs, unsigned short& ls) {
    __nv_bfloat16 h = __float2bfloat16_rn(v);
    float hf = __bfloat162float(h);
    __nv_bfloat16 l = __float2bfloat16_rn(v - hf);
    hs = __bfloat16_as_ushort(h);
    ls = __bfloat16_as_ushort(l);
}
__device__ __forceinline__ U32 packA(float v) {
    unsigned short hs, ls; bsplit(v, hs, ls);
    return (U32)hs | ((U32)ls << 16);
}

// Scratch (cudaMalloc forbidden; __device__ globals allowed)
__device__ U32   g_xp [1024 * 768];
__device__ U32   g_swh[256 * 768], g_swl[256 * 768];
__device__ U32   g_twh[256 * 768], g_twl[256 * 768];
__device__ U32   g_w2h[256 * 512], g_w2l[256 * 512];
__device__ U32   g_w3p[25 * 256];                 // fc3 tf32 bits, k-permuted
__device__ U32   g_s  [1024 * 256];               // stage1 out, packed-split, permuted
__device__ U32   g_t  [1024 * 256];
__device__ float g_s2 [1024 * 256];               // stage2 out, fp32, h-permuted
__device__ float g_t2 [1024 * 256];

#define NX  (1024 * 768)
#define NW  (256 * 768)
#define NW2 (256 * 512)
#define NW3 (25 * 256)
#define NX8  (NX  / 8)    // 98304
#define NW8  (NW  / 8)    // 24576
#define NW28 (NW2 / 8)    // 16384
#define NW38 (NW3 / 8)    // 800

// permutation within each 8-group: output pos p takes source element j,
// j = {0,4,1,5,2,6,3,7}  (the inverse of permk: permk(j) = p)
#define PERM_STORE(dst, o)                                              \
    do {                                                                \
        uint4* _d = (uint4*)(dst);                                      \
        _d[0] = make_uint4((o)[0], (o)[4], (o)[1], (o)[5]);             \
        _d[1] = make_uint4((o)[2], (o)[6], (o)[3], (o)[7]);             \
    } while (0)

// ---------------------------------------------------------------------------
// prep v2: fully vectorized — each thread handles one 8-element permutation
// group (LDG.128 in, permute in regs, STG.128 out; coalesced both ways).
// ---------------------------------------------------------------------------
__global__ void prep(const float* __restrict__ X,
                     const float* __restrict__ sw, const float* __restrict__ tw,
                     const float* __restrict__ w2, const float* __restrict__ w3)
{
    const int i = blockIdx.x * blockDim.x + threadIdx.x;

    if (i < NX8) {
        const int row = i / 96;             // 768/8 groups per row
        const int g8  = (i % 96) * 8;
        const float4* xs = (const float4*)(X + (size_t)row * 768 + g8);
        const float4 v0 = xs[0], v1 = xs[1];
        U32 o[8] = {packA(v0.x), packA(v0.y), packA(v0.z), packA(v0.w),
                    packA(v1.x), packA(v1.y), packA(v1.z), packA(v1.w)};
        PERM_STORE(g_xp + (size_t)row * 768 + g8, o);
    }
    if (i < NW8) {
        const int row = i / 96;
        const int g8  = (i % 96) * 8;
        const float4* ss = (const float4*)(sw + (size_t)row * 768 + g8);
        const float4* ts = (const float4*)(tw + (size_t)row * 768 + g8);
        const float4 sv0 = ss[0], sv1 = ss[1], tv0 = ts[0], tv1 = ts[1];
        const float se[8] = {sv0.x, sv0.y, sv0.z, sv0.w, sv1.x, sv1.y, sv1.z, sv1.w};
        const float te[8] = {tv0.x, tv0.y, tv0.z, tv0.w, tv1.x, tv1.y, tv1.z, tv1.w};
        U32 shh[8], sl0[8], thh[8], tl0[8];
#pragma unroll
        for (int e = 0; e < 8; e++) {
            unsigned short hs, ls;
            bsplit(se[e], hs, ls);
            shh[e] = (U32)hs | ((U32)hs << 16);
            sl0[e] = (U32)ls;
            bsplit(te[e], hs, ls);
            thh[e] = (U32)hs | ((U32)hs << 16);
            tl0[e] = (U32)ls;
        }
        const size_t o = (size_t)row * 768 + g8;
        PERM_STORE(g_swh + o, shh);
        PERM_STORE(g_swl + o, sl0);
        PERM_STORE(g_twh + o, thh);
        PERM_STORE(g_twl + o, tl0);
    }
    if (i < NW28) {
        const int row = i / 64;             // 512/8
        const int g8  = (i % 64) * 8;
        const float4* ws = (const float4*)(w2 + (size_t)row * 512 + g8);
        const float4 v0 = ws[0], v1 = ws[1];
        const float we[8] = {v0.x, v0.y, v0.z, v0.w, v1.x, v1.y, v1.z, v1.w};
        U32 whh[8], wl0[8];
#pragma unroll
        for (int e = 0; e < 8; e++) {
            unsigned short hs, ls;
            bsplit(we[e], hs, ls);
            whh[e] = (U32)hs | ((U32)hs << 16);
            wl0[e] = (U32)ls;
        }
        const size_t o = (size_t)row * 512 + g8;
        PERM_STORE(g_w2h + o, whh);
        PERM_STORE(g_w2l + o, wl0);
    }
    if (i < NW38) {
        const int row = i / 32;             // 256/8
        const int g8  = (i % 32) * 8;
        const float4* ws = (const float4*)(w3 + (size_t)row * 256 + g8);
        const float4 v0 = ws[0], v1 = ws[1];
        U32 o[8] = {tf32r(v0.x), tf32r(v0.y), tf32r(v0.z), tf32r(v0.w),
                    tf32r(v1.x), tf32r(v1.y), tf32r(v1.z), tf32r(v1.w)};
        PERM_STORE(g_w3p + (size_t)row * 256 + g8, o);
    }
}

// ---------------------------------------------------------------------------
// gemm_bf v5 (unchanged from R13 — best measured): 4-stage cp.async ring,
// 3 chunks in flight, ONE __syncthreads per chunk, commit every iteration.
// packed bf16-split (D += A x Bhh + A x Bl0, m16n8k16), pure LDS+MMA body.
// CTA 32m x 32n, 128 threads, K-chunk 32 words. 512 CTAs. smem 61.4 KB.
// packOut: 0 = plain fp32, 1 = packed-split U32 (permuted), 2 = fp32 permuted.
// ---------------------------------------------------------------------------
#define SKW 40
#define ARR (32 * SKW)
#define GBUF (3 * ARR)
#define NSTAGE 4
#define GEMM_SMEM (NSTAGE * GBUF * 4)      // 61440 bytes

__global__ __launch_bounds__(128) void gemm_bf(
    const U32* __restrict__ A0,  const U32* __restrict__ A1,
    const U32* __restrict__ Bh0, const U32* __restrict__ Bh1,
    const U32* __restrict__ Bl0, const U32* __restrict__ Bl1,
    const float* __restrict__ bias0, const float* __restrict__ bias1,
    void* C0, void* C1,
    int K, int ldb, int N, int relu, int packOut)
{
    extern __shared__ U32 smw[];

    const U32* A      = blockIdx.z ? A1 : A0;
    const U32* Bhp    = blockIdx.z ? Bh1 : Bh0;
    const U32* Blp    = blockIdx.z ? Bl1 : Bl0;
    const float* bias = blockIdx.z ? bias1 : bias0;
    void* C           = blockIdx.z ? C1 : C0;

    const int m0 = blockIdx.y * 32;
    const int n0 = blockIdx.x * 32;

    const int tid  = threadIdx.x;
    const int w    = tid >> 5;
    const int lane = tid & 31;
    const int g    = lane >> 2;
    const int tg   = lane & 3;
    const int r0   = (w & 1) * 16 + g;
    const int nb   = (w >> 1) * 16;

    const U32 smB = (U32)__cvta_generic_to_shared(smw);

    const int lrow = tid >> 2;
    const int lk   = (tid & 3) * 8;

    const U32* Aptr  = A   + (size_t)(m0 + lrow) * K   + lk;
    const U32* Bhptr = Bhp + (size_t)(n0 + lrow) * ldb + lk;
    const U32* Blptr = Blp + (size_t)(n0 + lrow) * ldb + lk;

    const int KC = K / 32;

    float acc[2][4];
#pragma unroll
    for (int nt = 0; nt < 2; nt++)
#pragma unroll
        for (int c = 0; c < 4; c++) acc[nt][c] = 0.f;

#pragma unroll
    for (int s = 0; s < 3; s++) {
        if (s < KC) {
            const int ko = s * 32;
            const U32 d = smB + s * GBUF * 4 + (lrow * SKW + lk) * 4;
#pragma unroll
            for (int c = 0; c < 2; c++) {
                cp16(d +            c * 16, Aptr  + ko + c * 4);
                cp16(d + ARR * 4  + c * 16, Bhptr + ko + c * 4);
                cp16(d + ARR * 8  + c * 16, Blptr + ko + c * 4);
            }
        }
        cp_commit();
    }

    for (int kc = 0; kc < KC; kc++) {
        const int cur = kc & (NSTAGE - 1);
        cp_wait2();
        __syncthreads();

        if (kc + 3 < KC) {
            const int ko = (kc + 3) * 32;
            const U32 d = smB + ((kc + 3) & (NSTAGE - 1)) * GBUF * 4
                        + (lrow * SKW + lk) * 4;
#pragma unroll
            for (int c = 0; c < 2; c++) {
                cp16(d +            c * 16, Aptr  + ko + c * 4);
                cp16(d + ARR * 4  + c * 16, Bhptr + ko + c * 4);
                cp16(d + ARR * 8  + c * 16, Blptr + ko + c * 4);
            }
        }
        cp_commit();

        const U32* base = smw + cur * GBUF;
#pragma unroll
        for (int ks = 0; ks < 4; ks++) {
            const int o = ks * 8 + 2 * tg;
            uint2 aA = *(const uint2*)&base[ r0      * SKW + o];
            uint2 aB = *(const uint2*)&base[(r0 + 8) * SKW + o];
#pragma unroll
            for (int nt = 0; nt < 2; nt++) {
                uint2 bh = *(const uint2*)&base[ARR     + (nb + nt * 8 + g) * SKW + o];
                uint2 bl = *(const uint2*)&base[ARR * 2 + (nb + nt * 8 + g) * SKW + o];
                mma_bf16(acc[nt][0], acc[nt][1], acc[nt][2], acc[nt][3],
                         aA.x, aB.x, aA.y, aB.y, bh.x, bh.y);
                mma_bf16(acc[nt][0], acc[nt][1], acc[nt][2], acc[nt][3],
                         aA.x, aB.x, aA.y, aB.y, bl.x, bl.y);
            }
        }
    }
    cp_wait0();

#pragma unroll
    for (int nt = 0; nt < 2; nt++) {
#pragma unroll
        for (int cc = 0; cc < 2; cc++) {
            const int r   = 2 * tg + cc;
            const int col = n0 + nb + nt * 8 + r;
            float bv = bias ? bias[col] : 0.f;
            float v0 = acc[nt][cc]     + bv;
            float v1 = acc[nt][cc + 2] + bv;
            if (relu) { v0 = fmaxf(v0, 0.f); v1 = fmaxf(v1, 0.f); }
            const int pcol = n0 + nb + nt * 8 + (((r & 3) << 1) | ((r >> 2) & 1));
            if (packOut == 1) {
                ((U32*)C)[(size_t)(m0 + r0)     * N + pcol] = packA(v0);
                ((U32*)C)[(size_t)(m0 + r0 + 8) * N + pcol] = packA(v1);
            } else if (packOut == 2) {
                ((float*)C)[(size_t)(m0 + r0)     * N + pcol] = v0;
                ((float*)C)[(size_t)(m0 + r0 + 8) * N + pcol] = v1;
            } else {
                ((float*)C)[(size_t)(m0 + r0)     * N + col] = v0;
                ((float*)C)[(size_t)(m0 + r0 + 8) * N + col] = v1;
            }
        }
    }
}

// ---------------------------------------------------------------------------
// pair_mma v5: v4 + packed add.rn.f32x2 for the pair construction (the
// (h,h+4) LDS.64 pairs are natural f32x2 operands; 8 FADD -> 4 FADD2/ks).
// smem 68.6 KB -> 3 CTAs/SM; staging pure cp.async from pre-permuted gmem.
// W stores only 25 real rows; nt=3 rows 25..31 alias the s region (finite
// floats) and feed only the discarded n>=25 output columns.
// ---------------------------------------------------------------------------
#define PROW 264
#define PROW2 132
#define SM_T2F 0
#define SM_WF  (32 * PROW)
#define SM_SF  (57 * PROW)
#define PAIR_SMEM (65 * PROW * 4)   // 68640 B

__global__ __launch_bounds__(256, 3) void pair_mma(
    const float* __restrict__ s2, const float* __restrict__ t2,
    const U32* __restrict__ w3p, float* __restrict__ out)
{
    extern __shared__ float sm[];
    const int jt = blockIdx.x;   // 0..7  (j tile of 32)
    const int ig = blockIdx.y;   // 0..31 (i group of 8)
    const int b  = blockIdx.z;   // 0..3

    const int tid  = threadIdx.x;
    const int w    = tid >> 5;
    const int lane = tid & 31;
    const int g    = lane >> 2;
    const int tg   = lane & 3;
    const int wj   = w & 1;
    const int wi   = w >> 1;

    const U32 smB = (U32)__cvta_generic_to_shared(sm);

    {   // t2: 32 rows x 256 floats
        const float* t2g = t2 + (size_t)(b * 256 + jt * 32) * 256;
#pragma unroll
        for (int r = 0; r < 8; r++) {
            int q   = tid + r * 256;
            int row = q >> 6;
            int c4  = (q & 63) * 4;
            cp16(smB + (SM_T2F + row * PROW + c4) * 4, t2g + row * 256 + c4);
        }
    }
    // fc3 tf32: 25 rows x 256
    for (int q = tid; q < 1600; q += 256) {
        int row = q >> 6;
        int c4  = (q & 63) * 4;
        cp16(smB + (SM_WF + row * PROW + c4) * 4, w3p + row * 256 + c4);
    }
    {   // s2: 8 rows x 256
        const float* s2g = s2 + (size_t)(b * 256 + ig * 8) * 256;
#pragma unroll
        for (int r = 0; r < 2; r++) {
            int q   = tid + r * 256;
            int row = q >> 6;
            int c4  = (q & 63) * 4;
            cp16(smB + (SM_SF + row * PROW + c4) * 4, s2g + row * 256 + c4);
        }
    }
    cp_commit();
    cp_wait0();
    __syncthreads();

    const float2* tA2 = (const float2*)sm + (size_t)(wj * 16 + g) * PROW2 + tg;
    const float2* tW2 = (const float2*)sm + (SM_WF / 2) + (size_t)g * PROW2 + tg;
    const float2* tS2 = (const float2*)sm + (SM_SF / 2) + (size_t)(wi * 2) * PROW2 + tg;

    float acc[2][4][4];   // [i][nt][c]
#pragma unroll
    for (int i = 0; i < 2; i++)
#pragma unroll
        for (int nt = 0; nt < 4; nt++)
#pragma unroll
            for (int c = 0; c < 4; c++) acc[i][nt][c] = 0.f;

#pragma unroll 4
    for (int ks = 0; ks < 32; ks++) {
        const int o = ks * 4;
        float2 u0 = tA2[o];
        float2 u1 = tA2[o + 8 * PROW2];
        float2 wv[4];
#pragma unroll
        for (int nt = 0; nt < 4; nt++) wv[nt] = tW2[o + nt * 8 * PROW2];
#pragma unroll
        for (int i = 0; i < 2; i++) {
            float2 sv = tS2[o + i * PROW2];
            float2 p0 = add2(u0, sv);    // (a0, a2) pre-relu
            float2 p1 = add2(u1, sv);    // (a1, a3) pre-relu
            U32 a0 = tf32r(fmaxf(p0.x, 0.f));
            U32 a1 = tf32r(fmaxf(p1.x, 0.f));
            U32 a2 = tf32r(fmaxf(p0.y, 0.f));
            U32 a3 = tf32r(fmaxf(p1.y, 0.f));
#pragma unroll
            for (int nt = 0; nt < 4; nt++) {
                mma_tf32(acc[i][nt][0], acc[i][nt][1], acc[i][nt][2], acc[i][nt][3],
                         a0, a1, a2, a3,
                         __float_as_uint(wv[nt].x), __float_as_uint(wv[nt].y));
            }
        }
    }

    const int jg = jt * 32 + wj * 16 + g;
#pragma unroll
    for (int i = 0; i < 2; i++) {
        const int ii = ig * 8 + wi * 2 + i;
        float* obase = out + ((size_t)(b * 256 + ii) * 25) * 256 + jg;
#pragma unroll
        for (int nt = 0; nt < 4; nt++) {
            int n0 = nt * 8 + tg * 2;
            if (n0 < 25) {
                obase[(size_t)n0 * 256]     = acc[i][nt][0];
                obase[(size_t)n0 * 256 + 8] = acc[i][nt][2];
            }
            if (n0 + 1 < 25) {
                obase[(size_t)(n0 + 1) * 256]     = acc[i][nt][1];
                obase[(size_t)(n0 + 1) * 256 + 8] = acc[i][nt][3];
            }
        }
    }
}

// ---------------------------------------------------------------------------
// Inputs (metadata order):
// 0 input_tensor [4,256,768]  1 s_fc_w [256,768]  2 s_fc_b [256]
// 3 t_fc_w [256,768]          4 t_fc_b [256]      5 fc2_w [256,512]
// 6 fc2_b [256]               7 fc3_w [25,256]
// Output: float32 [4,256,25,256]
// ---------------------------------------------------------------------------
extern "C" void kernel_launch(void* const* d_in, const int* in_sizes, int n_in,
                              void* d_out, int out_size)
{
    const float* X  = (const float*)d_in[0];
    const float* sw = (const float*)d_in[1];
    const float* sb = (const float*)d_in[2];
    const float* tw = (const float*)d_in[3];
    const float* tb = (const float*)d_in[4];
    const float* w2 = (const float*)d_in[5];
    const float* b2 = (const float*)d_in[6];
    const float* w3 = (const float*)d_in[7];
    float* out = (float*)d_out;

    U32 *xp, *swh, *swl, *twh, *twl, *w2h, *w2l, *w3p, *gs, *gt;
    float *gs2, *gt2;
    cudaGetSymbolAddress((void**)&xp,  g_xp);
    cudaGetSymbolAddress((void**)&swh, g_swh);
    cudaGetSymbolAddress((void**)&swl, g_swl);
    cudaGetSymbolAddress((void**)&twh, g_twh);
    cudaGetSymbolAddress((void**)&twl, g_twl);
    cudaGetSymbolAddress((void**)&w2h, g_w2h);
    cudaGetSymbolAddress((void**)&w2l, g_w2l);
    cudaGetSymbolAddress((void**)&w3p, g_w3p);
    cudaGetSymbolAddress((void**)&gs,  g_s);
    cudaGetSymbolAddress((void**)&gt,  g_t);
    cudaGetSymbolAddress((void**)&gs2, g_s2);
    cudaGetSymbolAddress((void**)&gt2, g_t2);

    cudaFuncSetAttribute(gemm_bf, cudaFuncAttributeMaxDynamicSharedMemorySize,
                         GEMM_SMEM);
    cudaFuncSetAttribute(pair_mma, cudaFuncAttributeMaxDynamicSharedMemorySize,
                         PAIR_SMEM);

    prep<<<(NX8 + 255) / 256, 256>>>(X, sw, tw, w2, w3);

    dim3 blk(128);
    dim3 g1(256 / 32, 1024 / 32, 2);   // 512 CTAs
    gemm_bf<<<g1, blk, GEMM_SMEM>>>(xp, xp, swh, twh, swl, twl, sb, tb,
                                    gs, gt, 768, 768, 256, 1, 1);
    // s2/t2 written fp32 with h-permutation (packOut=2) for pair staging
    gemm_bf<<<g1, blk, GEMM_SMEM>>>(gs, gt, w2h, w2h + 256, w2l, w2l + 256,
                                    nullptr, b2, gs2, gt2, 256, 512, 256, 0, 2);

    dim3 g3(8, 32, 4);                 // 1024 CTAs, 256 threads
    pair_mma<<<g3, dim3(256), PAIR_SMEM>>>(gs2, gt2, w3p, out);
}

// round 16
// speedup vs baseline: 1.1835x; 1.1835x over previous
#include <cuda_runtime.h>
#include <cuda_bf16.h>

typedef unsigned int U32;
typedef unsigned long long U64;

__device__ __forceinline__ U32 tf32r(float x) {
    U32 r;
    asm("cvt.rna.tf32.f32 %0, %1;" : "=r"(r) : "f"(x));
    return r;
}
__device__ __forceinline__ float2 add2(float2 a, float2 b) {
    U64 ua = *reinterpret_cast<U64*>(&a);
    U64 ub = *reinterpret_cast<U64*>(&b);
    U64 uc;
    asm("add.rn.f32x2 %0, %1, %2;" : "=l"(uc) : "l"(ua), "l"(ub));
    return *reinterpret_cast<float2*>(&uc);
}
__device__ __forceinline__ void mma_tf32(
    float& c0, float& c1, float& c2, float& c3,
    U32 a0, U32 a1, U32 a2, U32 a3, U32 b0, U32 b1)
{
    asm volatile(
        "mma.sync.aligned.m16n8k8.row.col.f32.tf32.tf32.f32 "
        "{%0,%1,%2,%3}, {%4,%5,%6,%7}, {%8,%9}, {%0,%1,%2,%3};"
        : "+f"(c0), "+f"(c1), "+f"(c2), "+f"(c3)
        : "r"(a0), "r"(a1), "r"(a2), "r"(a3), "r"(b0), "r"(b1));
}
__device__ __forceinline__ void mma_bf16(
    float& c0, float& c1, float& c2, float& c3,
    U32 a0, U32 a1, U32 a2, U32 a3, U32 b0, U32 b1)
{
    asm volatile(
        "mma.sync.aligned.m16n8k16.row.col.f32.bf16.bf16.f32 "
        "{%0,%1,%2,%3}, {%4,%5,%6,%7}, {%8,%9}, {%0,%1,%2,%3};"
        : "+f"(c0), "+f"(c1), "+f"(c2), "+f"(c3)
        : "r"(a0), "r"(a1), "r"(a2), "r"(a3), "r"(b0), "r"(b1));
}
__device__ __forceinline__ void cp16(U32 dst, const void* src) {
    asm volatile("cp.async.ca.shared.global [%0], [%1], 16;" :: "r"(dst), "l"(src));
}
__device__ __forceinline__ void cp_commit() { asm volatile("cp.async.commit_group;"); }
__device__ __forceinline__ void cp_wait1()  { asm volatile("cp.async.wait_group 1;"); }
__device__ __forceinline__ void cp_wait0()  { asm volatile("cp.async.wait_group 0;"); }

// bf16 hi/lo split. a = hi + lo + r, |r| <= 2^-18 |a|
__device__ __forceinline__ void bsplit(float v, unsigned short& hs, unsigned short& ls) {
    __nv_bfloat16 h = __float2bfloat16_rn(v);
    float hf = __bfloat162float(h);
    __nv_bfloat16 l = __float2bfloat16_rn(v - hf);
    hs = __bfloat16_as_ushort(h);
    ls = __bfloat16_as_ushort(l);
}
__device__ __forceinline__ U32 packA(float v) {
    unsigned short hs, ls; bsplit(v, hs, ls);
    return (U32)hs | ((U32)ls << 16);
}

// Scratch (cudaMalloc forbidden; __device__ globals allowed)
__device__ U32   g_xp [1024 * 768];
__device__ U32   g_swh[256 * 768], g_swl[256 * 768];
__device__ U32   g_twh[256 * 768], g_twl[256 * 768];
__device__ U32   g_w2h[256 * 512], g_w2l[256 * 512];
__device__ U32   g_w3p[25 * 256];                 // fc3 tf32 bits, k-permuted
__device__ U32   g_s  [1024 * 256];               // stage1 out, packed-split, permuted
__device__ U32   g_t  [1024 * 256];
__device__ float g_s2 [1024 * 256];               // stage2 out, tf32-rounded, h-permuted
__device__ float g_t2 [1024 * 256];

#define NX  (1024 * 768)
#define NW  (256 * 768)
#define NW2 (256 * 512)
#define NW3 (25 * 256)
#define NX8  (NX  / 8)
#define NW8  (NW  / 8)
#define NW28 (NW2 / 8)
#define NW38 (NW3 / 8)

// permutation within each 8-group: output pos p takes source element j,
// j = {0,4,1,5,2,6,3,7}  (inverse of permk)
#define PERM_STORE(dst, o)                                              \
    do {                                                                \
        uint4* _d = (uint4*)(dst);                                      \
        _d[0] = make_uint4((o)[0], (o)[4], (o)[1], (o)[5]);             \
        _d[1] = make_uint4((o)[2], (o)[6], (o)[3], (o)[7]);             \
    } while (0)

// ---------------------------------------------------------------------------
// prep v2 (unchanged, verified): vectorized 8-element permutation groups.
// ---------------------------------------------------------------------------
__global__ void prep(const float* __restrict__ X,
                     const float* __restrict__ sw, const float* __restrict__ tw,
                     const float* __restrict__ w2, const float* __restrict__ w3)
{
    const int i = blockIdx.x * blockDim.x + threadIdx.x;

    if (i < NX8) {
        const int row = i / 96;
        const int g8  = (i % 96) * 8;
        const float4* xs = (const float4*)(X + (size_t)row * 768 + g8);
        const float4 v0 = xs[0], v1 = xs[1];
        U32 o[8] = {packA(v0.x), packA(v0.y), packA(v0.z), packA(v0.w),
                    packA(v1.x), packA(v1.y), packA(v1.z), packA(v1.w)};
        PERM_STORE(g_xp + (size_t)row * 768 + g8, o);
    }
    if (i < NW8) {
        const int row = i / 96;
        const int g8  = (i % 96) * 8;
        const float4* ss = (const float4*)(sw + (size_t)row * 768 + g8);
        const float4* ts = (const float4*)(tw + (size_t)row * 768 + g8);
        const float4 sv0 = ss[0], sv1 = ss[1], tv0 = ts[0], tv1 = ts[1];
        const float se[8] = {sv0.x, sv0.y, sv0.z, sv0.w, sv1.x, sv1.y, sv1.z, sv1.w};
        const float te[8] = {tv0.x, tv0.y, tv0.z, tv0.w, tv1.x, tv1.y, tv1.z, tv1.w};
        U32 shh[8], sl0[8], thh[8], tl0[8];
#pragma unroll
        for (int e = 0; e < 8; e++) {
            unsigned short hs, ls;
            bsplit(se[e], hs, ls);
            shh[e] = (U32)hs | ((U32)hs << 16);
            sl0[e] = (U32)ls;
            bsplit(te[e], hs, ls);
            thh[e] = (U32)hs | ((U32)hs << 16);
            tl0[e] = (U32)ls;
        }
        const size_t o = (size_t)row * 768 + g8;
        PERM_STORE(g_swh + o, shh);
        PERM_STORE(g_swl + o, sl0);
        PERM_STORE(g_twh + o, thh);
        PERM_STORE(g_twl + o, tl0);
    }
    if (i < NW28) {
        const int row = i / 64;
        const int g8  = (i % 64) * 8;
        const float4* ws = (const float4*)(w2 + (size_t)row * 512 + g8);
        const float4 v0 = ws[0], v1 = ws[1];
        const float we[8] = {v0.x, v0.y, v0.z, v0.w, v1.x, v1.y, v1.z, v1.w};
        U32 whh[8], wl0[8];
#pragma unroll
        for (int e = 0; e < 8; e++) {
            unsigned short hs, ls;
            bsplit(we[e], hs, ls);
            whh[e] = (U32)hs | ((U32)hs << 16);
            wl0[e] = (U32)ls;
        }
        const size_t o = (size_t)row * 512 + g8;
        PERM_STORE(g_w2h + o, whh);
        PERM_STORE(g_w2l + o, wl0);
    }
    if (i < NW38) {
        const int row = i / 32;
        const int g8  = (i % 32) * 8;
        const float4* ws = (const float4*)(w3 + (size_t)row * 256 + g8);
        const float4 v0 = ws[0], v1 = ws[1];
        U32 o[8] = {tf32r(v0.x), tf32r(v0.y), tf32r(v0.z), tf32r(v0.w),
                    tf32r(v1.x), tf32r(v1.y), tf32r(v1.z), tf32r(v1.w)};
        PERM_STORE(g_w3p + (size_t)row * 256 + g8, o);
    }
}

// ---------------------------------------------------------------------------
// gemm_bf v6: 64m x 32n tile, 256 threads (8 warps: w>>1 = m-quarter,
// w&1 = n-half), 3-stage cp.async ring (wait_group 1, always-commit, one
// __syncthreads per chunk). Halves B weight re-reads vs the 32m tile
// (16 m-tiles instead of 32 -> gemm1 L2 traffic ~96 MB -> ~48 MB).
// Packed bf16-split (D += A x Bhh + A x Bl0, m16n8k16), pure LDS+MMA body.
// 256 CTAs. smem 60 KB -> 3 CTAs/SM (24 warps).
// packOut: 0 = plain fp32, 1 = packed-split U32 (permuted),
//          2 = tf32-ROUNDED fp32 (permuted) for the pair kernel.
// ---------------------------------------------------------------------------
#define SKW 40
#define A_WORDS (64 * SKW)                 // 2560
#define B_WORDS (32 * SKW)                 // 1280
#define OFF_BH  A_WORDS
#define OFF_BL  (A_WORDS + B_WORDS)
#define GBUF    (A_WORDS + 2 * B_WORDS)    // 5120 words
#define NSTAGE  3
#define GEMM_SMEM (NSTAGE * GBUF * 4)      // 61440 bytes

__global__ __launch_bounds__(256, 3) void gemm_bf(
    const U32* __restrict__ A0,  const U32* __restrict__ A1,
    const U32* __restrict__ Bh0, const U32* __restrict__ Bh1,
    const U32* __restrict__ Bl0, const U32* __restrict__ Bl1,
    const float* __restrict__ bias0, const float* __restrict__ bias1,
    void* C0, void* C1,
    int K, int ldb, int N, int relu, int packOut)
{
    extern __shared__ U32 smw[];

    const U32* A      = blockIdx.z ? A1 : A0;
    const U32* Bhp    = blockIdx.z ? Bh1 : Bh0;
    const U32* Blp    = blockIdx.z ? Bl1 : Bl0;
    const float* bias = blockIdx.z ? bias1 : bias0;
    void* C           = blockIdx.z ? C1 : C0;

    const int m0 = blockIdx.y * 64;
    const int n0 = blockIdx.x * 32;

    const int tid  = threadIdx.x;
    const int w    = tid >> 5;
    const int lane = tid & 31;
    const int g    = lane >> 2;
    const int tg   = lane & 3;
    const int r0   = (w >> 1) * 16 + g;    // m rows r0, r0+8 (0..63)
    const int nb   = (w & 1) * 16;         // n half

    const U32 smB = (U32)__cvta_generic_to_shared(smw);

    // loaders (256 threads):
    // A: row = tid>>2 (0..63), words (tid&3)*8 .. +7  -> 2 cp16
    // B: row = tid>>3 (0..31), words (tid&7)*4 .. +3  -> 1 cp16 each
    const int arow = tid >> 2;
    const int ak   = (tid & 3) * 8;
    const int brow = tid >> 3;
    const int bk   = (tid & 7) * 4;

    const U32* Aptr  = A   + (size_t)(m0 + arow) * K   + ak;
    const U32* Bhptr = Bhp + (size_t)(n0 + brow) * ldb + bk;
    const U32* Blptr = Blp + (size_t)(n0 + brow) * ldb + bk;

    const int KC = K / 32;

    float acc[2][4];
#pragma unroll
    for (int nt = 0; nt < 2; nt++)
#pragma unroll
        for (int c = 0; c < 4; c++) acc[nt][c] = 0.f;

    // prologue: chunks 0,1 into slots 0,1
#pragma unroll
    for (int s = 0; s < 2; s++) {
        if (s < KC) {
            const int ko = s * 32;
            const U32 base = smB + s * GBUF * 4;
            cp16(base + (arow * SKW + ak) * 4,      Aptr + ko);
            cp16(base + (arow * SKW + ak + 4) * 4,  Aptr + ko + 4);
            cp16(base + (OFF_BH + brow * SKW + bk) * 4, Bhptr + ko);
            cp16(base + (OFF_BL + brow * SKW + bk) * 4, Blptr + ko);
        }
        cp_commit();
    }

    for (int kc = 0; kc < KC; kc++) {
        const int cur = kc % NSTAGE;
        cp_wait1();              // completed >= kc+1  ->  chunk kc ready
        __syncthreads();

        // issue chunk kc+2 into slot (kc+2)%3 (= slot of chunk kc-1, freed)
        if (kc + 2 < KC) {
            const int ko = (kc + 2) * 32;
            const U32 base = smB + ((kc + 2) % NSTAGE) * GBUF * 4;
            cp16(base + (arow * SKW + ak) * 4,      Aptr + ko);
            cp16(base + (arow * SKW + ak + 4) * 4,  Aptr + ko + 4);
            cp16(base + (OFF_BH + brow * SKW + bk) * 4, Bhptr + ko);
            cp16(base + (OFF_BL + brow * SKW + bk) * 4, Blptr + ko);
        }
        cp_commit();             // always commit (possibly empty group)

        const U32* base = smw + cur * GBUF;
#pragma unroll
        for (int ks = 0; ks < 4; ks++) {
            const int o = ks * 8 + 2 * tg;
            uint2 aA = *(const uint2*)&base[ r0      * SKW + o];
            uint2 aB = *(const uint2*)&base[(r0 + 8) * SKW + o];
#pragma unroll
            for (int nt = 0; nt < 2; nt++) {
                uint2 bh = *(const uint2*)&base[OFF_BH + (nb + nt * 8 + g) * SKW + o];
                uint2 bl = *(const uint2*)&base[OFF_BL + (nb + nt * 8 + g) * SKW + o];
                mma_bf16(acc[nt][0], acc[nt][1], acc[nt][2], acc[nt][3],
                         aA.x, aB.x, aA.y, aB.y, bh.x, bh.y);
                mma_bf16(acc[nt][0], acc[nt][1], acc[nt][2], acc[nt][3],
                         aA.x, aB.x, aA.y, aB.y, bl.x, bl.y);
            }
        }
    }

    // epilogue: c0:(r0,2tg) c1:(r0,2tg+1) c2:(r0+8,2tg) c3:(r0+8,2tg+1)
#pragma unroll
    for (int nt = 0; nt < 2; nt++) {
#pragma unroll
        for (int cc = 0; cc < 2; cc++) {
            const int r   = 2 * tg + cc;
            const int col = n0 + nb + nt * 8 + r;
            float bv = bias ? bias[col] : 0.f;
            float v0 = acc[nt][cc]     + bv;
            float v1 = acc[nt][cc + 2] + bv;
            if (relu) { v0 = fmaxf(v0, 0.f); v1 = fmaxf(v1, 0.f); }
            const int pcol = n0 + nb + nt * 8 + (((r & 3) << 1) | ((r >> 2) & 1));
            if (packOut == 1) {
                ((U32*)C)[(size_t)(m0 + r0)     * N + pcol] = packA(v0);
                ((U32*)C)[(size_t)(m0 + r0 + 8) * N + pcol] = packA(v1);
            } else if (packOut == 2) {
                // tf32-rounded so the pair kernel can skip in-loop cvt
                ((U32*)C)[(size_t)(m0 + r0)     * N + pcol] = tf32r(v0);
                ((U32*)C)[(size_t)(m0 + r0 + 8) * N + pcol] = tf32r(v1);
            } else {
                ((float*)C)[(size_t)(m0 + r0)     * N + col] = v0;
                ((float*)C)[(size_t)(m0 + r0 + 8) * N + col] = v1;
            }
        }
    }
}

// ---------------------------------------------------------------------------
// pair_mma v6: s2/t2 arrive PRE-ROUNDED to tf32 -> the inner loop is
// LDS + add2 + fmax + MMA (no cvt; the sum's extra mantissa bit is
// truncated by the tensor core, error <= 2^-11 relative).
// smem 68.6 KB -> 3 CTAs/SM; staging pure cp.async from pre-permuted gmem.
// W stores only 25 real rows; nt=3 rows 25..31 alias the s region (finite
// floats) and feed only the discarded n>=25 output columns.
// ---------------------------------------------------------------------------
#define PROW 264
#define PROW2 132
#define SM_T2F 0
#define SM_WF  (32 * PROW)
#define SM_SF  (57 * PROW)
#define PAIR_SMEM (65 * PROW * 4)   // 68640 B

__global__ __launch_bounds__(256, 3) void pair_mma(
    const float* __restrict__ s2, const float* __restrict__ t2,
    const U32* __restrict__ w3p, float* __restrict__ out)
{
    extern __shared__ float sm[];
    const int jt = blockIdx.x;   // 0..7  (j tile of 32)
    const int ig = blockIdx.y;   // 0..31 (i group of 8)
    const int b  = blockIdx.z;   // 0..3

    const int tid  = threadIdx.x;
    const int w    = tid >> 5;
    const int lane = tid & 31;
    const int g    = lane >> 2;
    const int tg   = lane & 3;
    const int wj   = w & 1;
    const int wi   = w >> 1;

    const U32 smB = (U32)__cvta_generic_to_shared(sm);

    {   // t2: 32 rows x 256 floats
        const float* t2g = t2 + (size_t)(b * 256 + jt * 32) * 256;
#pragma unroll
        for (int r = 0; r < 8; r++) {
            int q   = tid + r * 256;
            int row = q >> 6;
            int c4  = (q & 63) * 4;
            cp16(smB + (SM_T2F + row * PROW + c4) * 4, t2g + row * 256 + c4);
        }
    }
    // fc3 tf32: 25 rows x 256
    for (int q = tid; q < 1600; q += 256) {
        int row = q >> 6;
        int c4  = (q & 63) * 4;
        cp16(smB + (SM_WF + row * PROW + c4) * 4, w3p + row * 256 + c4);
    }
    {   // s2: 8 rows x 256
        const float* s2g = s2 + (size_t)(b * 256 + ig * 8) * 256;
#pragma unroll
        for (int r = 0; r < 2; r++) {
            int q   = tid + r * 256;
            int row = q >> 6;
            int c4  = (q & 63) * 4;
            cp16(smB + (SM_SF + row * PROW + c4) * 4, s2g + row * 256 + c4);
        }
    }
    cp_commit();
    cp_wait0();
    __syncthreads();

    const float2* tA2 = (const float2*)sm + (size_t)(wj * 16 + g) * PROW2 + tg;
    const float2* tW2 = (const float2*)sm + (SM_WF / 2) + (size_t)g * PROW2 + tg;
    const float2* tS2 = (const float2*)sm + (SM_SF / 2) + (size_t)(wi * 2) * PROW2 + tg;

    float acc[2][4][4];   // [i][nt][c]
#pragma unroll
    for (int i = 0; i < 2; i++)
#pragma unroll
        for (int nt = 0; nt < 4; nt++)
#pragma unroll
            for (int c = 0; c < 4; c++) acc[i][nt][c] = 0.f;

#pragma unroll 4
    for (int ks = 0; ks < 32; ks++) {
        const int o = ks * 4;
        float2 u0 = tA2[o];
        float2 u1 = tA2[o + 8 * PROW2];
        float2 wv[4];
#pragma unroll
        for (int nt = 0; nt < 4; nt++) wv[nt] = tW2[o + nt * 8 * PROW2];
#pragma unroll
        for (int i = 0; i < 2; i++) {
            float2 sv = tS2[o + i * PROW2];
            float2 p0 = add2(u0, sv);    // operands pre-rounded to tf32
            float2 p1 = add2(u1, sv);
            U32 a0 = __float_as_uint(fmaxf(p0.x, 0.f));
            U32 a1 = __float_as_uint(fmaxf(p1.x, 0.f));
            U32 a2 = __float_as_uint(fmaxf(p0.y, 0.f));
            U32 a3 = __float_as_uint(fmaxf(p1.y, 0.f));
#pragma unroll
            for (int nt = 0; nt < 4; nt++) {
                mma_tf32(acc[i][nt][0], acc[i][nt][1], acc[i][nt][2], acc[i][nt][3],
                         a0, a1, a2, a3,
                         __float_as_uint(wv[nt].x), __float_as_uint(wv[nt].y));
            }
        }
    }

    const int jg = jt * 32 + wj * 16 + g;
#pragma unroll
    for (int i = 0; i < 2; i++) {
        const int ii = ig * 8 + wi * 2 + i;
        float* obase = out + ((size_t)(b * 256 + ii) * 25) * 256 + jg;
#pragma unroll
        for (int nt = 0; nt < 4; nt++) {
            int n0 = nt * 8 + tg * 2;
            if (n0 < 25) {
                obase[(size_t)n0 * 256]     = acc[i][nt][0];
                obase[(size_t)n0 * 256 + 8] = acc[i][nt][2];
            }
            if (n0 + 1 < 25) {
                obase[(size_t)(n0 + 1) * 256]     = acc[i][nt][1];
                obase[(size_t)(n0 + 1) * 256 + 8] = acc[i][nt][3];
            }
        }
    }
}

// ---------------------------------------------------------------------------
// Inputs (metadata order):
// 0 input_tensor [4,256,768]  1 s_fc_w [256,768]  2 s_fc_b [256]
// 3 t_fc_w [256,768]          4 t_fc_b [256]      5 fc2_w [256,512]
// 6 fc2_b [256]               7 fc3_w [25,256]
// Output: float32 [4,256,25,256]
// ---------------------------------------------------------------------------
extern "C" void kernel_launch(void* const* d_in, const int* in_sizes, int n_in,
                              void* d_out, int out_size)
{
    const float* X  = (const float*)d_in[0];
    const float* sw = (const float*)d_in[1];
    const float* sb = (const float*)d_in[2];
    const float* tw = (const float*)d_in[3];
    const float* tb = (const float*)d_in[4];
    const float* w2 = (const float*)d_in[5];
    const float* b2 = (const float*)d_in[6];
    const float* w3 = (const float*)d_in[7];
    float* out = (float*)d_out;

    U32 *xp, *swh, *swl, *twh, *twl, *w2h, *w2l, *w3p, *gs, *gt;
    float *gs2, *gt2;
    cudaGetSymbolAddress((void**)&xp,  g_xp);
    cudaGetSymbolAddress((void**)&swh, g_swh);
    cudaGetSymbolAddress((void**)&swl, g_swl);
    cudaGetSymbolAddress((void**)&twh, g_twh);
    cudaGetSymbolAddress((void**)&twl, g_twl);
    cudaGetSymbolAddress((void**)&w2h, g_w2h);
    cudaGetSymbolAddress((void**)&w2l, g_w2l);
    cudaGetSymbolAddress((void**)&w3p, g_w3p);
    cudaGetSymbolAddress((void**)&gs,  g_s);
    cudaGetSymbolAddress((void**)&gt,  g_t);
    cudaGetSymbolAddress((void**)&gs2, g_s2);
    cudaGetSymbolAddress((void**)&gt2, g_t2);

    cudaFuncSetAttribute(gemm_bf, cudaFuncAttributeMaxDynamicSharedMemorySize,
                         GEMM_SMEM);
    cudaFuncSetAttribute(pair_mma, cudaFuncAttributeMaxDynamicSharedMemorySize,
                         PAIR_SMEM);

    prep<<<(NX8 + 255) / 256, 256>>>(X, sw, tw, w2, w3);

    dim3 blk(256);
    dim3 g1(256 / 32, 1024 / 64, 2);   // 8 x 16 x 2 = 256 CTAs
    gemm_bf<<<g1, blk, GEMM_SMEM>>>(xp, xp, swh, twh, swl, twl, sb, tb,
                                    gs, gt, 768, 768, 256, 1, 1);
    // s2/t2 written tf32-rounded + h-permuted (packOut=2) for pair
    gemm_bf<<<g1, blk, GEMM_SMEM>>>(gs, gt, w2h, w2h + 256, w2l, w2l + 256,
                                    nullptr, b2, gs2, gt2, 256, 512, 256, 0, 2);

    dim3 g3(8, 32, 4);                 // 1024 CTAs, 256 threads
    pair_mma<<<g3, dim3(256), PAIR_SMEM>>>(gs2, gt2, w3p, out);
}

// round 17
// speedup vs baseline: 1.1874x; 1.0033x over previous
#include <cuda_runtime.h>
#include <cuda_bf16.h>

typedef unsigned int U32;
typedef unsigned long long U64;

__device__ __forceinline__ U32 tf32r(float x) {
    U32 r;
    asm("cvt.rna.tf32.f32 %0, %1;" : "=r"(r) : "f"(x));
    return r;
}
__device__ __forceinline__ float2 add2(float2 a, float2 b) {
    U64 ua = *reinterpret_cast<U64*>(&a);
    U64 ub = *reinterpret_cast<U64*>(&b);
    U64 uc;
    asm("add.rn.f32x2 %0, %1, %2;" : "=l"(uc) : "l"(ua), "l"(ub));
    return *reinterpret_cast<float2*>(&uc);
}
__device__ __forceinline__ void mma_tf32(
    float& c0, float& c1, float& c2, float& c3,
    U32 a0, U32 a1, U32 a2, U32 a3, U32 b0, U32 b1)
{
    asm volatile(
        "mma.sync.aligned.m16n8k8.row.col.f32.tf32.tf32.f32 "
        "{%0,%1,%2,%3}, {%4,%5,%6,%7}, {%8,%9}, {%0,%1,%2,%3};"
        : "+f"(c0), "+f"(c1), "+f"(c2), "+f"(c3)
        : "r"(a0), "r"(a1), "r"(a2), "r"(a3), "r"(b0), "r"(b1));
}
__device__ __forceinline__ void mma_bf16(
    float& c0, float& c1, float& c2, float& c3,
    U32 a0, U32 a1, U32 a2, U32 a3, U32 b0, U32 b1)
{
    asm volatile(
        "mma.sync.aligned.m16n8k16.row.col.f32.bf16.bf16.f32 "
        "{%0,%1,%2,%3}, {%4,%5,%6,%7}, {%8,%9}, {%0,%1,%2,%3};"
        : "+f"(c0), "+f"(c1), "+f"(c2), "+f"(c3)
        : "r"(a0), "r"(a1), "r"(a2), "r"(a3), "r"(b0), "r"(b1));
}
__device__ __forceinline__ void cp16(U32 dst, const void* src) {
    asm volatile("cp.async.ca.shared.global [%0], [%1], 16;" :: "r"(dst), "l"(src));
}
__device__ __forceinline__ void cp_commit() { asm volatile("cp.async.commit_group;"); }
__device__ __forceinline__ void cp_wait1()  { asm volatile("cp.async.wait_group 1;"); }
__device__ __forceinline__ void cp_wait0()  { asm volatile("cp.async.wait_group 0;"); }

// bf16 hi/lo split. a = hi + lo + r, |r| <= 2^-18 |a|
__device__ __forceinline__ void bsplit(float v, unsigned short& hs, unsigned short& ls) {
    __nv_bfloat16 h = __float2bfloat16_rn(v);
    float hf = __bfloat162float(h);
    __nv_bfloat16 l = __float2bfloat16_rn(v - hf);
    hs = __bfloat16_as_ushort(h);
    ls = __bfloat16_as_ushort(l);
}
__device__ __forceinline__ U32 packA(float v) {
    unsigned short hs, ls; bsplit(v, hs, ls);
    return (U32)hs | ((U32)ls << 16);
}

// Scratch (cudaMalloc forbidden; __device__ globals allowed)
__device__ U32   g_xp [1024 * 768];
__device__ U32   g_swh[256 * 768], g_swl[256 * 768];
__device__ U32   g_twh[256 * 768], g_twl[256 * 768];
__device__ U32   g_w2h[256 * 512], g_w2l[256 * 512];
__device__ U32   g_w3p[25 * 256];                 // fc3 tf32 bits, k-permuted
__device__ U32   g_s  [1024 * 256];               // stage1 out, packed-split, permuted
__device__ U32   g_t  [1024 * 256];
__device__ float g_s2 [1024 * 256];               // stage2 out, tf32-rounded, h-permuted
__device__ float g_t2 [1024 * 256];

#define NX  (1024 * 768)
#define NW  (256 * 768)
#define NW2 (256 * 512)
#define NW3 (25 * 256)
#define NX8  (NX  / 8)
#define NW8  (NW  / 8)
#define NW28 (NW2 / 8)
#define NW38 (NW3 / 8)

// permutation within each 8-group: output pos p takes source element j,
// j = {0,4,1,5,2,6,3,7}  (inverse of permk)
#define PERM_STORE(dst, o)                                              \
    do {                                                                \
        uint4* _d = (uint4*)(dst);                                      \
        _d[0] = make_uint4((o)[0], (o)[4], (o)[1], (o)[5]);             \
        _d[1] = make_uint4((o)[2], (o)[6], (o)[3], (o)[7]);             \
    } while (0)

// ---------------------------------------------------------------------------
// prep v2 (unchanged): vectorized 8-element permutation groups.
// ---------------------------------------------------------------------------
__global__ void prep(const float* __restrict__ X,
                     const float* __restrict__ sw, const float* __restrict__ tw,
                     const float* __restrict__ w2, const float* __restrict__ w3)
{
    const int i = blockIdx.x * blockDim.x + threadIdx.x;

    if (i < NX8) {
        const int row = i / 96;
        const int g8  = (i % 96) * 8;
        const float4* xs = (const float4*)(X + (size_t)row * 768 + g8);
        const float4 v0 = xs[0], v1 = xs[1];
        U32 o[8] = {packA(v0.x), packA(v0.y), packA(v0.z), packA(v0.w),
                    packA(v1.x), packA(v1.y), packA(v1.z), packA(v1.w)};
        PERM_STORE(g_xp + (size_t)row * 768 + g8, o);
    }
    if (i < NW8) {
        const int row = i / 96;
        const int g8  = (i % 96) * 8;
        const float4* ss = (const float4*)(sw + (size_t)row * 768 + g8);
        const float4* ts = (const float4*)(tw + (size_t)row * 768 + g8);
        const float4 sv0 = ss[0], sv1 = ss[1], tv0 = ts[0], tv1 = ts[1];
        const float se[8] = {sv0.x, sv0.y, sv0.z, sv0.w, sv1.x, sv1.y, sv1.z, sv1.w};
        const float te[8] = {tv0.x, tv0.y, tv0.z, tv0.w, tv1.x, tv1.y, tv1.z, tv1.w};
        U32 shh[8], sl0[8], thh[8], tl0[8];
#pragma unroll
        for (int e = 0; e < 8; e++) {
            unsigned short hs, ls;
            bsplit(se[e], hs, ls);
            shh[e] = (U32)hs | ((U32)hs << 16);
            sl0[e] = (U32)ls;
            bsplit(te[e], hs, ls);
            thh[e] = (U32)hs | ((U32)hs << 16);
            tl0[e] = (U32)ls;
        }
        const size_t o = (size_t)row * 768 + g8;
        PERM_STORE(g_swh + o, shh);
        PERM_STORE(g_swl + o, sl0);
        PERM_STORE(g_twh + o, thh);
        PERM_STORE(g_twl + o, tl0);
    }
    if (i < NW28) {
        const int row = i / 64;
        const int g8  = (i % 64) * 8;
        const float4* ws = (const float4*)(w2 + (size_t)row * 512 + g8);
        const float4 v0 = ws[0], v1 = ws[1];
        const float we[8] = {v0.x, v0.y, v0.z, v0.w, v1.x, v1.y, v1.z, v1.w};
        U32 whh[8], wl0[8];
#pragma unroll
        for (int e = 0; e < 8; e++) {
            unsigned short hs, ls;
            bsplit(we[e], hs, ls);
            whh[e] = (U32)hs | ((U32)hs << 16);
            wl0[e] = (U32)ls;
        }
        const size_t o = (size_t)row * 512 + g8;
        PERM_STORE(g_w2h + o, whh);
        PERM_STORE(g_w2l + o, wl0);
    }
    if (i < NW38) {
        const int row = i / 32;
        const int g8  = (i % 32) * 8;
        const float4* ws = (const float4*)(w3 + (size_t)row * 256 + g8);
        const float4 v0 = ws[0], v1 = ws[1];
        U32 o[8] = {tf32r(v0.x), tf32r(v0.y), tf32r(v0.z), tf32r(v0.w),
                    tf32r(v1.x), tf32r(v1.y), tf32r(v1.z), tf32r(v1.w)};
        PERM_STORE(g_w3p + (size_t)row * 256 + g8, o);
    }
}

// ---------------------------------------------------------------------------
// gemm_bf v6 (unchanged — measured good): 64m x 32n tile, 256 threads,
// 3-stage cp.async ring, one __syncthreads per chunk.
// packOut: 0 = plain fp32, 1 = packed-split U32 (permuted),
//          2 = tf32-ROUNDED fp32 (permuted) for the pair kernel.
// ---------------------------------------------------------------------------
#define SKW 40
#define A_WORDS (64 * SKW)
#define B_WORDS (32 * SKW)
#define OFF_BH  A_WORDS
#define OFF_BL  (A_WORDS + B_WORDS)
#define GBUF    (A_WORDS + 2 * B_WORDS)
#define NSTAGE  3
#define GEMM_SMEM (NSTAGE * GBUF * 4)      // 61440 bytes

__global__ __launch_bounds__(256, 3) void gemm_bf(
    const U32* __restrict__ A0,  const U32* __restrict__ A1,
    const U32* __restrict__ Bh0, const U32* __restrict__ Bh1,
    const U32* __restrict__ Bl0, const U32* __restrict__ Bl1,
    const float* __restrict__ bias0, const float* __restrict__ bias1,
    void* C0, void* C1,
    int K, int ldb, int N, int relu, int packOut)
{
    extern __shared__ U32 smw[];

    const U32* A      = blockIdx.z ? A1 : A0;
    const U32* Bhp    = blockIdx.z ? Bh1 : Bh0;
    const U32* Blp    = blockIdx.z ? Bl1 : Bl0;
    const float* bias = blockIdx.z ? bias1 : bias0;
    void* C           = blockIdx.z ? C1 : C0;

    const int m0 = blockIdx.y * 64;
    const int n0 = blockIdx.x * 32;

    const int tid  = threadIdx.x;
    const int w    = tid >> 5;
    const int lane = tid & 31;
    const int g    = lane >> 2;
    const int tg   = lane & 3;
    const int r0   = (w >> 1) * 16 + g;
    const int nb   = (w & 1) * 16;

    const U32 smB = (U32)__cvta_generic_to_shared(smw);

    const int arow = tid >> 2;
    const int ak   = (tid & 3) * 8;
    const int brow = tid >> 3;
    const int bk   = (tid & 7) * 4;

    const U32* Aptr  = A   + (size_t)(m0 + arow) * K   + ak;
    const U32* Bhptr = Bhp + (size_t)(n0 + brow) * ldb + bk;
    const U32* Blptr = Blp + (size_t)(n0 + brow) * ldb + bk;

    const int KC = K / 32;

    float acc[2][4];
#pragma unroll
    for (int nt = 0; nt < 2; nt++)
#pragma unroll
        for (int c = 0; c < 4; c++) acc[nt][c] = 0.f;

#pragma unroll
    for (int s = 0; s < 2; s++) {
        if (s < KC) {
            const int ko = s * 32;
            const U32 base = smB + s * GBUF * 4;
            cp16(base + (arow * SKW + ak) * 4,      Aptr + ko);
            cp16(base + (arow * SKW + ak + 4) * 4,  Aptr + ko + 4);
            cp16(base + (OFF_BH + brow * SKW + bk) * 4, Bhptr + ko);
            cp16(base + (OFF_BL + brow * SKW + bk) * 4, Blptr + ko);
        }
        cp_commit();
    }

    for (int kc = 0; kc < KC; kc++) {
        const int cur = kc % NSTAGE;
        cp_wait1();
        __syncthreads();

        if (kc + 2 < KC) {
            const int ko = (kc + 2) * 32;
            const U32 base = smB + ((kc + 2) % NSTAGE) * GBUF * 4;
            cp16(base + (arow * SKW + ak) * 4,      Aptr + ko);
            cp16(base + (arow * SKW + ak + 4) * 4,  Aptr + ko + 4);
            cp16(base + (OFF_BH + brow * SKW + bk) * 4, Bhptr + ko);
            cp16(base + (OFF_BL + brow * SKW + bk) * 4, Blptr + ko);
        }
        cp_commit();

        const U32* base = smw + cur * GBUF;
#pragma unroll
        for (int ks = 0; ks < 4; ks++) {
            const int o = ks * 8 + 2 * tg;
            uint2 aA = *(const uint2*)&base[ r0      * SKW + o];
            uint2 aB = *(const uint2*)&base[(r0 + 8) * SKW + o];
#pragma unroll
            for (int nt = 0; nt < 2; nt++) {
                uint2 bh = *(const uint2*)&base[OFF_BH + (nb + nt * 8 + g) * SKW + o];
                uint2 bl = *(const uint2*)&base[OFF_BL + (nb + nt * 8 + g) * SKW + o];
                mma_bf16(acc[nt][0], acc[nt][1], acc[nt][2], acc[nt][3],
                         aA.x, aB.x, aA.y, aB.y, bh.x, bh.y);
                mma_bf16(acc[nt][0], acc[nt][1], acc[nt][2], acc[nt][3],
                         aA.x, aB.x, aA.y, aB.y, bl.x, bl.y);
            }
        }
    }

#pragma unroll
    for (int nt = 0; nt < 2; nt++) {
#pragma unroll
        for (int cc = 0; cc < 2; cc++) {
            const int r   = 2 * tg + cc;
            const int col = n0 + nb + nt * 8 + r;
            float bv = bias ? bias[col] : 0.f;
            float v0 = acc[nt][cc]     + bv;
            float v1 = acc[nt][cc + 2] + bv;
            if (relu) { v0 = fmaxf(v0, 0.f); v1 = fmaxf(v1, 0.f); }
            const int pcol = n0 + nb + nt * 8 + (((r & 3) << 1) | ((r >> 2) & 1));
            if (packOut == 1) {
                ((U32*)C)[(size_t)(m0 + r0)     * N + pcol] = packA(v0);
                ((U32*)C)[(size_t)(m0 + r0 + 8) * N + pcol] = packA(v1);
            } else if (packOut == 2) {
                ((U32*)C)[(size_t)(m0 + r0)     * N + pcol] = tf32r(v0);
                ((U32*)C)[(size_t)(m0 + r0 + 8) * N + pcol] = tf32r(v1);
            } else {
                ((float*)C)[(size_t)(m0 + r0)     * N + col] = v0;
                ((float*)C)[(size_t)(m0 + r0 + 8) * N + col] = v1;
            }
        }
    }
}

// ---------------------------------------------------------------------------
// pair_mma v7: i-block 4 per warp (i-group 16). Per ks: 10 LDS.64 for
// 16 MMAs (1.25 wavefronts/MMA vs 2.0 in v6) — t and W fragments amortized
// over 4 i. acc = 64 regs -> launch_bounds(256,2), 2 CTAs/SM (16 warps).
// s2/t2 arrive PRE-ROUNDED to tf32 (no cvt in loop).
// smem 77.1 KB (t 32 + W 25 + s 16 rows). W stores only 25 real rows;
// nt=3 rows 25..31 alias s rows 0..6 + W row 24 (finite floats) and feed
// only the discarded n>=25 output columns.
// ---------------------------------------------------------------------------
#define PROW 264
#define PROW2 132
#define SM_T2F 0
#define SM_WF  (32 * PROW)          // W rows 32..56
#define SM_SF  (57 * PROW)          // s rows 57..72
#define PAIR_SMEM (73 * PROW * 4)   // 77088 B

__global__ __launch_bounds__(256, 2) void pair_mma(
    const float* __restrict__ s2, const float* __restrict__ t2,
    const U32* __restrict__ w3p, float* __restrict__ out)
{
    extern __shared__ float sm[];
    const int jt = blockIdx.x;   // 0..7  (j tile of 32)
    const int ig = blockIdx.y;   // 0..15 (i group of 16)
    const int b  = blockIdx.z;   // 0..3

    const int tid  = threadIdx.x;
    const int w    = tid >> 5;
    const int lane = tid & 31;
    const int g    = lane >> 2;
    const int tg   = lane & 3;
    const int wj   = w & 1;       // j half
    const int wi   = w >> 1;      // i quarter (0..3), 4 i-rows each

    const U32 smB = (U32)__cvta_generic_to_shared(sm);

    {   // t2: 32 rows x 256 floats
        const float* t2g = t2 + (size_t)(b * 256 + jt * 32) * 256;
#pragma unroll
        for (int r = 0; r < 8; r++) {
            int q   = tid + r * 256;
            int row = q >> 6;
            int c4  = (q & 63) * 4;
            cp16(smB + (SM_T2F + row * PROW + c4) * 4, t2g + row * 256 + c4);
        }
    }
    // fc3 tf32: 25 rows x 256
    for (int q = tid; q < 1600; q += 256) {
        int row = q >> 6;
        int c4  = (q & 63) * 4;
        cp16(smB + (SM_WF + row * PROW + c4) * 4, w3p + row * 256 + c4);
    }
    {   // s2: 16 rows x 256 = 1024 float4
        const float* s2g = s2 + (size_t)(b * 256 + ig * 16) * 256;
#pragma unroll
        for (int r = 0; r < 4; r++) {
            int q   = tid + r * 256;
            int row = q >> 6;
            int c4  = (q & 63) * 4;
            cp16(smB + (SM_SF + row * PROW + c4) * 4, s2g + row * 256 + c4);
        }
    }
    cp_commit();
    cp_wait0();
    __syncthreads();

    const float2* tA2 = (const float2*)sm + (size_t)(wj * 16 + g) * PROW2 + tg;
    const float2* tW2 = (const float2*)sm + (SM_WF / 2) + (size_t)g * PROW2 + tg;
    const float2* tS2 = (const float2*)sm + ((57 * PROW) / 2) + (size_t)(wi * 4) * PROW2 + tg;

    float acc[4][4][4];   // [i][nt][c] = 64 regs
#pragma unroll
    for (int i = 0; i < 4; i++)
#pragma unroll
        for (int nt = 0; nt < 4; nt++)
#pragma unroll
            for (int c = 0; c < 4; c++) acc[i][nt][c] = 0.f;

#pragma unroll 2
    for (int ks = 0; ks < 32; ks++) {
        const int o = ks * 4;
        float2 u0 = tA2[o];
        float2 u1 = tA2[o + 8 * PROW2];
        float2 wv[4];
#pragma unroll
        for (int nt = 0; nt < 4; nt++) wv[nt] = tW2[o + nt * 8 * PROW2];
#pragma unroll
        for (int i = 0; i < 4; i++) {
            float2 sv = tS2[o + i * PROW2];
            float2 p0 = add2(u0, sv);    // operands pre-rounded to tf32
            float2 p1 = add2(u1, sv);
            U32 a0 = __float_as_uint(fmaxf(p0.x, 0.f));
            U32 a1 = __float_as_uint(fmaxf(p1.x, 0.f));
            U32 a2 = __float_as_uint(fmaxf(p0.y, 0.f));
            U32 a3 = __float_as_uint(fmaxf(p1.y, 0.f));
#pragma unroll
            for (int nt = 0; nt < 4; nt++) {
                mma_tf32(acc[i][nt][0], acc[i][nt][1], acc[i][nt][2], acc[i][nt][3],
                         a0, a1, a2, a3,
                         __float_as_uint(wv[nt].x), __float_as_uint(wv[nt].y));
            }
        }
    }

    const int jg = jt * 32 + wj * 16 + g;
#pragma unroll
    for (int i = 0; i < 4; i++) {
        const int ii = ig * 16 + wi * 4 + i;
        float* obase = out + ((size_t)(b * 256 + ii) * 25) * 256 + jg;
#pragma unroll
        for (int nt = 0; nt < 4; nt++) {
            int n0 = nt * 8 + tg * 2;
            if (n0 < 25) {
                obase[(size_t)n0 * 256]     = acc[i][nt][0];
                obase[(size_t)n0 * 256 + 8] = acc[i][nt][2];
            }
            if (n0 + 1 < 25) {
                obase[(size_t)(n0 + 1) * 256]     = acc[i][nt][1];
                obase[(size_t)(n0 + 1) * 256 + 8] = acc[i][nt][3];
            }
        }
    }
}

// ---------------------------------------------------------------------------
// Inputs (metadata order):
// 0 input_tensor [4,256,768]  1 s_fc_w [256,768]  2 s_fc_b [256]
// 3 t_fc_w [256,768]          4 t_fc_b [256]      5 fc2_w [256,512]
// 6 fc2_b [256]               7 fc3_w [25,256]
// Output: float32 [4,256,25,256]
// ---------------------------------------------------------------------------
extern "C" void kernel_launch(void* const* d_in, const int* in_sizes, int n_in,
                              void* d_out, int out_size)
{
    const float* X  = (const float*)d_in[0];
    const float* sw = (const float*)d_in[1];
    const float* sb = (const float*)d_in[2];
    const float* tw = (const float*)d_in[3];
    const float* tb = (const float*)d_in[4];
    const float* w2 = (const float*)d_in[5];
    const float* b2 = (const float*)d_in[6];
    const float* w3 = (const float*)d_in[7];
    float* out = (float*)d_out;

    U32 *xp, *swh, *swl, *twh, *twl, *w2h, *w2l, *w3p, *gs, *gt;
    float *gs2, *gt2;
    cudaGetSymbolAddress((void**)&xp,  g_xp);
    cudaGetSymbolAddress((void**)&swh, g_swh);
    cudaGetSymbolAddress((void**)&swl, g_swl);
    cudaGetSymbolAddress((void**)&twh, g_twh);
    cudaGetSymbolAddress((void**)&twl, g_twl);
    cudaGetSymbolAddress((void**)&w2h, g_w2h);
    cudaGetSymbolAddress((void**)&w2l, g_w2l);
    cudaGetSymbolAddress((void**)&w3p, g_w3p);
    cudaGetSymbolAddress((void**)&gs,  g_s);
    cudaGetSymbolAddress((void**)&gt,  g_t);
    cudaGetSymbolAddress((void**)&gs2, g_s2);
    cudaGetSymbolAddress((void**)&gt2, g_t2);

    cudaFuncSetAttribute(gemm_bf, cudaFuncAttributeMaxDynamicSharedMemorySize,
                         GEMM_SMEM);
    cudaFuncSetAttribute(pair_mma, cudaFuncAttributeMaxDynamicSharedMemorySize,
                         PAIR_SMEM);

    prep<<<(NX8 + 255) / 256, 256>>>(X, sw, tw, w2, w3);

    dim3 blk(256);
    dim3 g1(256 / 32, 1024 / 64, 2);   // 256 CTAs
    gemm_bf<<<g1, blk, GEMM_SMEM>>>(xp, xp, swh, twh, swl, twl, sb, tb,
                                    gs, gt, 768, 768, 256, 1, 1);
    // s2/t2 written tf32-rounded + h-permuted (packOut=2) for pair
    gemm_bf<<<g1, blk, GEMM_SMEM>>>(gs, gt, w2h, w2h + 256, w2l, w2l + 256,
                                    nullptr, b2, gs2, gt2, 256, 512, 256, 0, 2);

    dim3 g3(8, 16, 4);                 // 512 CTAs, 256 threads
    pair_mma<<<g3, dim3(256), PAIR_SMEM>>>(gs2, gt2, w3p, out);
}